// round 14
// baseline (speedup 1.0000x reference)
#include <cuda_runtime.h>
#include <cstdint>

#define NB 4
#define NL 1024
#define ND 1024
#define NA 1024
#define NH 16
#define NDH 64
#define NM (NB*NL)
#define FSCALE 0.03125f
#define LN_EPS 1e-5f
#define MFL ((size_t)1<<20)

// 80MB float pool (intermediates only; inputs read directly)
__device__ float g_scratch[(size_t)20 * MFL];
#define F_QH   ((size_t)0)
#define F_KH   (4*MFL)
#define F_VT   (8*MFL)
#define F_CTX  (12*MFL)
#define F_O1   (16*MFL)

__device__ __forceinline__ uint32_t f2tf32(float f) {
    uint32_t u; asm("cvt.rna.tf32.f32 %0, %1;" : "=r"(u) : "f"(f)); return u;
}
__device__ __forceinline__ uint32_t u2tf32(uint32_t b) {
    uint32_t u; asm("cvt.rna.tf32.f32 %0, %1;" : "=r"(u) : "f"(__uint_as_float(b))); return u;
}
__device__ __forceinline__ void mma_tf32(float* d, const uint32_t* a, const uint32_t* b) {
    asm volatile("mma.sync.aligned.m16n8k8.row.col.f32.tf32.tf32.f32 "
        "{%0,%1,%2,%3}, {%4,%5,%6,%7}, {%8,%9}, {%0,%1,%2,%3};\n"
        : "+f"(d[0]), "+f"(d[1]), "+f"(d[2]), "+f"(d[3])
        : "r"(a[0]), "r"(a[1]), "r"(a[2]), "r"(a[3]), "r"(b[0]), "r"(b[1]));
}
__device__ __forceinline__ void ldsm_x4(uint32_t* r, uint32_t addr) {
    asm volatile("ldmatrix.sync.aligned.m8n8.x4.shared.b16 {%0,%1,%2,%3}, [%4];"
        : "=r"(r[0]), "=r"(r[1]), "=r"(r[2]), "=r"(r[3]) : "r"(addr));
}
__device__ __forceinline__ void cp_async16(uint32_t s, const void* g) {
    asm volatile("cp.async.cg.shared.global [%0], [%1], 16;\n" :: "r"(s), "l"(g));
}
__device__ __forceinline__ void cp_commit() { asm volatile("cp.async.commit_group;\n"); }
template<int N> __device__ __forceinline__ void cp_wait() { asm volatile("cp.async.wait_group %0;\n" :: "n"(N)); }

// -------- tf32 GEMM, 128x128 tile, KC=32, 2-stage, ldmatrix + in-loop cvt --
// Raw f32 inputs; fragments rounded to tf32 post-LDSM (bit-identical to a
// pre-rounding pass; cvt is idempotent on the already-rounded CTX operand).
#define KC 32
#define SPAD 36
#define BUF_FLT (128 * SPAD)
#define GEMM_SMEM (2 * BUF_FLT * 2 * 4)   // 73728 bytes

__global__ __launch_bounds__(256)
void gemm_all(int opBase,
              const float* __restrict__ x,   const float* __restrict__ qu,
              const float* __restrict__ Wqs, const float* __restrict__ Wqo,
              const float* __restrict__ Wk,  const float* __restrict__ Wv,
              const float* __restrict__ Wo,  const float* __restrict__ bo,
              float* __restrict__ pool)
{
    extern __shared__ float smf[];
    float* AsB = smf;
    float* BsB = smf + 2 * BUF_FLT;

    const int op = opBase + blockIdx.z;
    const float *A0, *A1, *B0, *B1; float* C; int NCH, mode;
    if (op == 0)      { A0=x;           A1=qu; B0=Wqs; B1=Wqo; C=pool+F_QH; NCH=64; mode=5; }
    else if (op == 1) { A0=x;           A1=x;  B0=Wk;  B1=Wk;  C=pool+F_KH; NCH=32; mode=5; }
    else if (op == 2) { A0=x;           A1=x;  B0=Wv;  B1=Wv;  C=pool+F_VT; NCH=32; mode=3; }
    else              { A0=pool+F_CTX;  A1=A0; B0=Wo;  B1=Wo;  C=pool+F_O1; NCH=32; mode=1; }

    const int tid  = threadIdx.x;
    const int lane = tid & 31;
    const int wid  = tid >> 5;
    const int g    = lane >> 2;
    const int tig  = lane & 3;
    const int wm   = (wid >> 2) << 6;
    const int wn   = (wid & 3) << 5;
    const int rowBase = blockIdx.y << 7;
    const int colBase = blockIdx.x << 7;

    const uint32_t smA = __cvta_generic_to_shared(AsB);
    const uint32_t smB = __cvta_generic_to_shared(BsB);
    const uint32_t bufStride = BUF_FLT * 4;

    const int rr = lane & 7, qq = lane >> 3;
    uint32_t aoff[4], boff[2];
#pragma unroll
    for (int mt = 0; mt < 4; mt++)
        aoff[mt] = ((wm + mt * 16 + (qq & 1) * 8 + rr) * SPAD + (qq >> 1) * 4) * 4;
#pragma unroll
    for (int p = 0; p < 2; p++)
        boff[p] = ((wn + p * 16 + (qq >> 1) * 8 + rr) * SPAD + (qq & 1) * 4) * 4;

    auto load_chunk = [&](int kt, int buf) {
        const float* Asrc; const float* Bsrc; int kcol;
        if (kt >= 32) { Asrc = A1; Bsrc = B1; kcol = (kt - 32) * KC; }
        else          { Asrc = A0; Bsrc = B0; kcol = kt * KC; }
        const uint32_t off = buf * bufStride;
#pragma unroll
        for (int i = 0; i < 4; i++) {
            const int u = tid + i * 256;
            const int row = u >> 3, kg = u & 7;
            const uint32_t d = off + (row * SPAD + kg * 4) * 4;
            cp_async16(smA + d, Asrc + (size_t)(rowBase + row) * ND + kcol + kg * 4);
            cp_async16(smB + d, Bsrc + (size_t)(colBase + row) * ND + kcol + kg * 4);
        }
        cp_commit();
    };

    float acc[4][4][4];
#pragma unroll
    for (int mt = 0; mt < 4; mt++)
#pragma unroll
        for (int nt = 0; nt < 4; nt++)
#pragma unroll
            for (int e = 0; e < 4; e++) acc[mt][nt][e] = 0.f;

    load_chunk(0, 0);

    for (int kt = 0; kt < NCH; kt++) {
        cp_wait<0>();
        __syncthreads();
        if (kt + 1 < NCH) load_chunk(kt + 1, (kt + 1) & 1);

        const uint32_t bo32 = (kt & 1) * bufStride;
#pragma unroll
        for (int ks = 0; ks < 4; ks++) {
            uint32_t afr[4][4], bfr[4][2], t[4];
#pragma unroll
            for (int mt = 0; mt < 4; mt++) {
                ldsm_x4(afr[mt], smA + bo32 + aoff[mt] + ks * 32);
                afr[mt][0] = u2tf32(afr[mt][0]); afr[mt][1] = u2tf32(afr[mt][1]);
                afr[mt][2] = u2tf32(afr[mt][2]); afr[mt][3] = u2tf32(afr[mt][3]);
            }
#pragma unroll
            for (int p = 0; p < 2; p++) {
                ldsm_x4(t, smB + bo32 + boff[p] + ks * 32);
                bfr[2*p][0]   = u2tf32(t[0]); bfr[2*p][1]   = u2tf32(t[1]);
                bfr[2*p+1][0] = u2tf32(t[2]); bfr[2*p+1][1] = u2tf32(t[3]);
            }
#pragma unroll
            for (int mt = 0; mt < 4; mt++)
#pragma unroll
                for (int nt = 0; nt < 4; nt++)
                    mma_tf32(acc[mt][nt], afr[mt], bfr[nt]);
        }
    }

    // epilogue
    if (mode <= 1) {
#pragma unroll
        for (int mt = 0; mt < 4; mt++) {
            const int row0 = rowBase + wm + mt * 16 + g;
#pragma unroll
            for (int nt = 0; nt < 4; nt++) {
                const int col = colBase + wn + nt * 8 + tig * 2;
                float2 bj = *(const float2*)&bo[col];
                *(float2*)&C[(size_t)row0 * NA + col] =
                    make_float2(acc[mt][nt][0] + bj.x, acc[mt][nt][1] + bj.y);
                *(float2*)&C[(size_t)(row0 + 8) * NA + col] =
                    make_float2(acc[mt][nt][2] + bj.x, acc[mt][nt][3] + bj.y);
            }
        }
    } else if (mode == 3) {
        const int bb = rowBase >> 10;
        const int lB = (rowBase & (NL - 1));
#pragma unroll
        for (int mt = 0; mt < 4; mt++) {
            const int l0 = lB + wm + mt * 16 + g;
#pragma unroll
            for (int nt = 0; nt < 4; nt++) {
                const int a = colBase + wn + nt * 8 + tig * 2;
                float* cp0 = C + (size_t)(bb * NA + a) * NL;
                float* cp1 = C + (size_t)(bb * NA + a + 1) * NL;
                cp0[l0]     = __uint_as_float(f2tf32(acc[mt][nt][0]));
                cp1[l0]     = __uint_as_float(f2tf32(acc[mt][nt][1]));
                cp0[l0 + 8] = __uint_as_float(f2tf32(acc[mt][nt][2]));
                cp1[l0 + 8] = __uint_as_float(f2tf32(acc[mt][nt][3]));
            }
        }
    } else {  // mode 5
        const int bb = rowBase >> 10;
        const int lB = (rowBase & (NL - 1));
#pragma unroll
        for (int mt = 0; mt < 4; mt++) {
            const int l0 = lB + wm + mt * 16 + g;
#pragma unroll
            for (int nt = 0; nt < 4; nt++) {
                const int a = colBase + wn + nt * 8 + tig * 2;
                const int hh = a >> 6, d = a & 63;
                float* cp = C + ((size_t)(bb * NH + hh) * NL + l0) * NDH + d;
                *(float2*)cp = make_float2(__uint_as_float(f2tf32(acc[mt][nt][0])),
                                           __uint_as_float(f2tf32(acc[mt][nt][1])));
                *(float2*)(cp + 8 * NDH) = make_float2(__uint_as_float(f2tf32(acc[mt][nt][2])),
                                                       __uint_as_float(f2tf32(acc[mt][nt][3])));
            }
        }
    }
}

// ------ flash attention: no-max softmax, cp.async K/V, raw-f32 P store -----
#define ATT_LD 68
#define ATT_TILE (64 * ATT_LD)
#define ATT_SMEM ((4 * ATT_TILE + 8 * 16 * ATT_LD) * 4 + NL * 4)  // 108544 B

__global__ __launch_bounds__(256, 2)
void attn_tc(const float* __restrict__ pool_c, float* __restrict__ pool,
             const int* __restrict__ mask)
{
    extern __shared__ uint32_t sm[];
    uint32_t* Ks = sm;
    uint32_t* Vs = Ks + 2 * ATT_TILE;
    uint32_t* Ps = Vs + 2 * ATT_TILE;
    float* msks = (float*)(Ps + 8 * 16 * ATT_LD);

    const int tid = threadIdx.x, lane = tid & 31, wid = tid >> 5;
    const int g = lane >> 2, tig = lane & 3;
    const int qb = blockIdx.x, bh = blockIdx.y;
    const int b = bh >> 4, hoff = (bh & 15) * NDH;

    const float* Qbase = pool_c + F_QH + ((size_t)bh * NL + qb * 128) * NDH;
    const float* Kbase = pool_c + F_KH + (size_t)bh * NL * NDH;
    const float* Vbase = pool_c + F_VT + (size_t)(b * NA + hoff) * NL;
    float* Ctx = pool + F_CTX;
    uint32_t* Pw = Ps + wid * 16 * ATT_LD;

    const int rr = lane & 7, qq = lane >> 3;
    const uint32_t ksb = __cvta_generic_to_shared(Ks);
    const uint32_t vsb = __cvta_generic_to_shared(Vs);
    const uint32_t pwb = __cvta_generic_to_shared(Pw);
    const uint32_t tileB = ATT_TILE * 4;
    uint32_t kvoff[4];
#pragma unroll
    for (int p = 0; p < 4; p++)
        kvoff[p] = ((p * 16 + (qq >> 1) * 8 + rr) * ATT_LD + (qq & 1) * 4) * 4;
    const uint32_t apoff = (((qq & 1) * 8 + rr) * ATT_LD + (qq >> 1) * 4) * 4;

    const int lr = tid >> 2, lc = (tid & 3) << 2;
    auto load_tile = [&](int jb, int buf) {
        const uint32_t off = buf * tileB;
#pragma unroll
        for (int i = 0; i < 4; i++) {
            const int c4 = lc + (i << 4);
            const uint32_t d = off + (lr * ATT_LD + c4) * 4;
            cp_async16(ksb + d, &Kbase[(size_t)(jb * 64 + lr) * 64 + c4]);
            cp_async16(vsb + d, &Vbase[(size_t)lr * NL + jb * 64 + c4]);
        }
        cp_commit();
    };

    for (int i = tid; i < NL; i += 256)
        msks[i] = (1.0f - (float)mask[b * NL + i]) * -100000.0f;

    uint32_t aq[8][4];
    {
        const int r0 = wid * 16 + g;
#pragma unroll
        for (int ks = 0; ks < 8; ks++) {
            aq[ks][0] = __float_as_uint(Qbase[(size_t)r0     * 64 + ks*8 + tig    ] * FSCALE);
            aq[ks][1] = __float_as_uint(Qbase[(size_t)(r0+8) * 64 + ks*8 + tig    ] * FSCALE);
            aq[ks][2] = __float_as_uint(Qbase[(size_t)r0     * 64 + ks*8 + tig + 4] * FSCALE);
            aq[ks][3] = __float_as_uint(Qbase[(size_t)(r0+8) * 64 + ks*8 + tig + 4] * FSCALE);
        }
    }

    float oacc[8][4];
#pragma unroll
    for (int nt = 0; nt < 8; nt++)
#pragma unroll
        for (int e = 0; e < 4; e++) oacc[nt][e] = 0.f;
    float lr0 = 0.f, lr1 = 0.f;

    load_tile(0, 0);

    for (int jb = 0; jb < 16; jb++) {
        cp_wait<0>();
        __syncthreads();
        if (jb + 1 < 16) load_tile(jb + 1, (jb + 1) & 1);

        const uint32_t bo32 = (jb & 1) * tileB;

        float s[8][4];
#pragma unroll
        for (int nt = 0; nt < 8; nt++)
            s[nt][0] = s[nt][1] = s[nt][2] = s[nt][3] = 0.f;
#pragma unroll
        for (int ks = 0; ks < 8; ks++) {
#pragma unroll
            for (int p = 0; p < 4; p++) {
                uint32_t t[4];
                ldsm_x4(t, ksb + bo32 + kvoff[p] + ks * 32);
                mma_tf32(s[2*p],   aq[ks], &t[0]);
                mma_tf32(s[2*p+1], aq[ks], &t[2]);
            }
        }

        float rs0 = 0.f, rs1 = 0.f;
#pragma unroll
        for (int nt = 0; nt < 8; nt++) {
            float2 mv = *(const float2*)&msks[jb*64 + nt*8 + tig*2];
            s[nt][0] = __expf(s[nt][0] + mv.x); rs0 += s[nt][0];
            s[nt][1] = __expf(s[nt][1] + mv.y); rs0 += s[nt][1];
            s[nt][2] = __expf(s[nt][2] + mv.x); rs1 += s[nt][2];
            s[nt][3] = __expf(s[nt][3] + mv.y); rs1 += s[nt][3];
        }
        rs0 += __shfl_xor_sync(0xffffffffu, rs0, 1);
        rs0 += __shfl_xor_sync(0xffffffffu, rs0, 2);
        rs1 += __shfl_xor_sync(0xffffffffu, rs1, 1);
        rs1 += __shfl_xor_sync(0xffffffffu, rs1, 2);
        lr0 += rs0;
        lr1 += rs1;

        __syncwarp();
#pragma unroll
        for (int nt = 0; nt < 8; nt++) {
            *(uint2*)&Pw[g       * ATT_LD + nt*8 + tig*2] =
                make_uint2(__float_as_uint(s[nt][0]), __float_as_uint(s[nt][1]));
            *(uint2*)&Pw[(g + 8) * ATT_LD + nt*8 + tig*2] =
                make_uint2(__float_as_uint(s[nt][2]), __float_as_uint(s[nt][3]));
        }
        __syncwarp();

#pragma unroll
        for (int ks = 0; ks < 8; ks++) {
            uint32_t ap[4];
            ldsm_x4(ap, pwb + apoff + ks * 32);
#pragma unroll
            for (int p = 0; p < 4; p++) {
                uint32_t t[4];
                ldsm_x4(t, vsb + bo32 + kvoff[p] + ks * 32);
                mma_tf32(oacc[2*p],   ap, &t[0]);
                mma_tf32(oacc[2*p+1], ap, &t[2]);
            }
        }
    }

    const float inv0 = 1.0f / lr0, inv1 = 1.0f / lr1;
    const int q0 = qb * 128 + wid * 16 + g;
    float* Ob = Ctx + ((size_t)(b * NL + q0)) * NA + hoff;
#pragma unroll
    for (int nt = 0; nt < 8; nt++) {
        const int co = nt * 8 + tig * 2;
        *(float2*)&Ob[co] = make_float2(
            __uint_as_float(f2tf32(oacc[nt][0] * inv0)),
            __uint_as_float(f2tf32(oacc[nt][1] * inv0)));
        *(float2*)&Ob[(size_t)8 * NA + co] = make_float2(
            __uint_as_float(f2tf32(oacc[nt][2] * inv1)),
            __uint_as_float(f2tf32(oacc[nt][3] * inv1)));
    }
}

// ---------------- LayerNorm ----------------
__global__ __launch_bounds__(256)
void ln_kernel(const float* __restrict__ X, const float* __restrict__ gamma,
               const float* __restrict__ beta, float* __restrict__ out)
{
    __shared__ float ssum[8], ssq[8];
    const int row = blockIdx.x, tid = threadIdx.x;
    const float* xr = X + (size_t)row * NA;
    float4 v = *(const float4*)&xr[tid*4];
    float s = v.x + v.y + v.z + v.w;
    float s2 = v.x*v.x + v.y*v.y + v.z*v.z + v.w*v.w;
#pragma unroll
    for (int o = 16; o > 0; o >>= 1) {
        s  += __shfl_xor_sync(0xffffffffu, s,  o);
        s2 += __shfl_xor_sync(0xffffffffu, s2, o);
    }
    if ((tid & 31) == 0) { ssum[tid>>5] = s; ssq[tid>>5] = s2; }
    __syncthreads();
    float ts = 0.f, ts2 = 0.f;
#pragma unroll
    for (int i = 0; i < 8; i++) { ts += ssum[i]; ts2 += ssq[i]; }
    const float mu = ts * (1.f/1024.f);
    const float var = ts2 * (1.f/1024.f) - mu*mu;
    const float rstd = rsqrtf(var + LN_EPS);
    float4 gm = *(const float4*)&gamma[tid*4];
    float4 be = *(const float4*)&beta[tid*4];
    float4 o;
    o.x = (v.x - mu)*rstd*gm.x + be.x;
    o.y = (v.y - mu)*rstd*gm.y + be.y;
    o.z = (v.z - mu)*rstd*gm.z + be.z;
    o.w = (v.w - mu)*rstd*gm.w + be.w;
    *(float4*)&out[(size_t)row*NA + tid*4] = o;
}

// ---------------------------------------------------------------------------
extern "C" void kernel_launch(void* const* d_in, const int* in_sizes, int n_in,
                              void* d_out, int out_size)
{
    const float* x   = (const float*)d_in[0];
    const float* qu  = (const float*)d_in[1];
    const float* Wk  = (const float*)d_in[2];
    const float* Wqs = (const float*)d_in[3];
    const float* Wqo = (const float*)d_in[4];
    const float* Wv  = (const float*)d_in[5];
    const float* Wo  = (const float*)d_in[6];
    const float* bo  = (const float*)d_in[7];
    const float* gam = (const float*)d_in[8];
    const float* bet = (const float*)d_in[9];
    const int*   msk = (const int*)d_in[10];
    float* out = (float*)d_out;

    float* pool = nullptr;
    cudaGetSymbolAddress((void**)&pool, g_scratch);

    static bool attrSet = false;
    if (!attrSet) {
        cudaFuncSetAttribute(gemm_all, cudaFuncAttributeMaxDynamicSharedMemorySize, GEMM_SMEM);
        cudaFuncSetAttribute(attn_tc, cudaFuncAttributeMaxDynamicSharedMemorySize, ATT_SMEM);
        attrSet = true;
    }

    gemm_all<<<dim3(NA/128, NM/128, 3), 256, GEMM_SMEM>>>(
        0, x, qu, Wqs, Wqo, Wk, Wv, Wo, bo, pool);

    attn_tc<<<dim3(NL/128, NB*NH), 256, ATT_SMEM>>>(pool, pool, msk);

    gemm_all<<<dim3(NA/128, NM/128, 1), 256, GEMM_SMEM>>>(
        3, x, qu, Wqs, Wqo, Wk, Wv, Wo, bo, pool);

    ln_kernel<<<NM, 256>>>(pool + F_O1, gam, bet, out);
}

// round 16
// speedup vs baseline: 1.0523x; 1.0523x over previous
#include <cuda_runtime.h>
#include <cstdint>

#define NB 4
#define NL 1024
#define ND 1024
#define NA 1024
#define NH 16
#define NDH 64
#define NM (NB*NL)
#define FSCALE 0.03125f
#define LN_EPS 1e-5f
#define MFL ((size_t)1<<20)

// 132MB float pool
__device__ float g_scratch[(size_t)33 * MFL];
#define F_QH   ((size_t)0)
#define F_KH   (4*MFL)
#define F_VT   (8*MFL)
#define F_CTX  (12*MFL)
#define F_O1   (16*MFL)
#define F_XR   (20*MFL)
#define F_QUR  (24*MFL)
#define F_WQS  (28*MFL)
#define F_WQO  (29*MFL)
#define F_WK   (30*MFL)
#define F_WV   (31*MFL)
#define F_WO   (32*MFL)

__device__ __forceinline__ uint32_t f2tf32(float f) {
    uint32_t u; asm("cvt.rna.tf32.f32 %0, %1;" : "=r"(u) : "f"(f)); return u;
}
__device__ __forceinline__ void mma_tf32(float* d, const uint32_t* a, const uint32_t* b) {
    asm volatile("mma.sync.aligned.m16n8k8.row.col.f32.tf32.tf32.f32 "
        "{%0,%1,%2,%3}, {%4,%5,%6,%7}, {%8,%9}, {%0,%1,%2,%3};\n"
        : "+f"(d[0]), "+f"(d[1]), "+f"(d[2]), "+f"(d[3])
        : "r"(a[0]), "r"(a[1]), "r"(a[2]), "r"(a[3]), "r"(b[0]), "r"(b[1]));
}
__device__ __forceinline__ void ldsm_x4(uint32_t* r, uint32_t addr) {
    asm volatile("ldmatrix.sync.aligned.m8n8.x4.shared.b16 {%0,%1,%2,%3}, [%4];"
        : "=r"(r[0]), "=r"(r[1]), "=r"(r[2]), "=r"(r[3]) : "r"(addr));
}
__device__ __forceinline__ void cp_async16(uint32_t s, const void* g) {
    asm volatile("cp.async.cg.shared.global [%0], [%1], 16;\n" :: "r"(s), "l"(g));
}
__device__ __forceinline__ void cp_commit() { asm volatile("cp.async.commit_group;\n"); }
template<int N> __device__ __forceinline__ void cp_wait() { asm volatile("cp.async.wait_group %0;\n" :: "n"(N)); }

// ---------------- pre-pass: round tensors to tf32-in-f32 ----------------
__global__ __launch_bounds__(256)
void round_kernel(const float* __restrict__ x, const float* __restrict__ qu,
                  const float* __restrict__ Wqs, const float* __restrict__ Wqo,
                  const float* __restrict__ Wk, const float* __restrict__ Wv,
                  const float* __restrict__ Wo, float* __restrict__ pool)
{
    const float* src; float* dst; int n;
    switch (blockIdx.z) {
        case 0: src=x;   dst=pool+F_XR;  n=NM*ND; break;
        case 1: src=qu;  dst=pool+F_QUR; n=NM*ND; break;
        case 2: src=Wqs; dst=pool+F_WQS; n=NA*ND; break;
        case 3: src=Wqo; dst=pool+F_WQO; n=NA*ND; break;
        case 4: src=Wk;  dst=pool+F_WK;  n=NA*ND; break;
        case 5: src=Wv;  dst=pool+F_WV;  n=NA*ND; break;
        default: src=Wo; dst=pool+F_WO;  n=NA*ND; break;
    }
    const int i4 = (blockIdx.x * 256 + threadIdx.x) * 4;
    if (i4 >= n) return;
    float4 v = *(const float4*)(src + i4);
    uint4 o;
    o.x = f2tf32(v.x); o.y = f2tf32(v.y); o.z = f2tf32(v.z); o.w = f2tf32(v.w);
    *(uint4*)(dst + i4) = o;
}

// -------- tf32 GEMM, 128x128 tile, KC=32, 2-stage, ldmatrix (pre-rounded) --
// per chunk: sync (buffer free) -> issue load(kt+1) -> wait own group(kt) ->
// sync (all threads' chunk-kt writes visible) -> compute.
#define KC 32
#define SPAD 36
#define BUF_FLT (128 * SPAD)
#define GEMM_SMEM (2 * BUF_FLT * 2 * 4)   // 73728 bytes

__global__ __launch_bounds__(256)
void gemm_all(int opBase, const float* __restrict__ pool_c,
              const float* __restrict__ bo, float* __restrict__ pool)
{
    extern __shared__ float smf[];
    float* AsB = smf;
    float* BsB = smf + 2 * BUF_FLT;

    const int op = opBase + blockIdx.z;
    const float *A0, *A1, *B0, *B1; float* C; int NCH, mode;
    if (op == 0)      { A0=pool_c+F_XR;  A1=pool_c+F_QUR; B0=pool_c+F_WQS; B1=pool_c+F_WQO; C=pool+F_QH; NCH=64; mode=5; }
    else if (op == 1) { A0=pool_c+F_XR;  A1=A0;           B0=pool_c+F_WK;  B1=B0;           C=pool+F_KH; NCH=32; mode=5; }
    else if (op == 2) { A0=pool_c+F_XR;  A1=A0;           B0=pool_c+F_WV;  B1=B0;           C=pool+F_VT; NCH=32; mode=3; }
    else              { A0=pool_c+F_CTX; A1=A0;           B0=pool_c+F_WO;  B1=B0;           C=pool+F_O1; NCH=32; mode=1; }

    const int tid  = threadIdx.x;
    const int lane = tid & 31;
    const int wid  = tid >> 5;
    const int g    = lane >> 2;
    const int tig  = lane & 3;
    const int wm   = (wid >> 2) << 6;
    const int wn   = (wid & 3) << 5;
    const int rowBase = blockIdx.y << 7;
    const int colBase = blockIdx.x << 7;

    const uint32_t smA = __cvta_generic_to_shared(AsB);
    const uint32_t smB = __cvta_generic_to_shared(BsB);
    const uint32_t bufStride = BUF_FLT * 4;

    const int rr = lane & 7, qq = lane >> 3;
    uint32_t aoff[4], boff[2];
#pragma unroll
    for (int mt = 0; mt < 4; mt++)
        aoff[mt] = ((wm + mt * 16 + (qq & 1) * 8 + rr) * SPAD + (qq >> 1) * 4) * 4;
#pragma unroll
    for (int p = 0; p < 2; p++)
        boff[p] = ((wn + p * 16 + (qq >> 1) * 8 + rr) * SPAD + (qq & 1) * 4) * 4;

    auto load_chunk = [&](int kt, int buf) {
        const float* Asrc; const float* Bsrc; int kcol;
        if (kt >= 32) { Asrc = A1; Bsrc = B1; kcol = (kt - 32) * KC; }
        else          { Asrc = A0; Bsrc = B0; kcol = kt * KC; }
        const uint32_t off = buf * bufStride;
#pragma unroll
        for (int i = 0; i < 4; i++) {
            const int u = tid + i * 256;
            const int row = u >> 3, kg = u & 7;
            const uint32_t d = off + (row * SPAD + kg * 4) * 4;
            cp_async16(smA + d, Asrc + (size_t)(rowBase + row) * ND + kcol + kg * 4);
            cp_async16(smB + d, Bsrc + (size_t)(colBase + row) * ND + kcol + kg * 4);
        }
        cp_commit();
    };

    float acc[4][4][4];
#pragma unroll
    for (int mt = 0; mt < 4; mt++)
#pragma unroll
        for (int nt = 0; nt < 4; nt++)
#pragma unroll
            for (int e = 0; e < 4; e++) acc[mt][nt][e] = 0.f;

    load_chunk(0, 0);

    for (int kt = 0; kt < NCH; kt++) {
        __syncthreads();                      // compute(kt-1) done: buffer free
        if (kt + 1 < NCH) {
            load_chunk(kt + 1, (kt + 1) & 1); // issue next before waiting
            cp_wait<1>();                     // own chunk-kt group landed
        } else {
            cp_wait<0>();
        }
        __syncthreads();                      // all threads' chunk-kt visible

        const uint32_t bo32 = (kt & 1) * bufStride;
#pragma unroll
        for (int ks = 0; ks < 4; ks++) {
            uint32_t afr[4][4], bfr[4][2], t[4];
#pragma unroll
            for (int mt = 0; mt < 4; mt++)
                ldsm_x4(afr[mt], smA + bo32 + aoff[mt] + ks * 32);
#pragma unroll
            for (int p = 0; p < 2; p++) {
                ldsm_x4(t, smB + bo32 + boff[p] + ks * 32);
                bfr[2*p][0] = t[0]; bfr[2*p][1] = t[1];
                bfr[2*p+1][0] = t[2]; bfr[2*p+1][1] = t[3];
            }
#pragma unroll
            for (int mt = 0; mt < 4; mt++)
#pragma unroll
                for (int nt = 0; nt < 4; nt++)
                    mma_tf32(acc[mt][nt], afr[mt], bfr[nt]);
        }
    }

    // epilogue
    if (mode <= 1) {
#pragma unroll
        for (int mt = 0; mt < 4; mt++) {
            const int row0 = rowBase + wm + mt * 16 + g;
#pragma unroll
            for (int nt = 0; nt < 4; nt++) {
                const int col = colBase + wn + nt * 8 + tig * 2;
                float2 bj = *(const float2*)&bo[col];
                *(float2*)&C[(size_t)row0 * NA + col] =
                    make_float2(acc[mt][nt][0] + bj.x, acc[mt][nt][1] + bj.y);
                *(float2*)&C[(size_t)(row0 + 8) * NA + col] =
                    make_float2(acc[mt][nt][2] + bj.x, acc[mt][nt][3] + bj.y);
            }
        }
    } else if (mode == 3) {
        const int bb = rowBase >> 10;
        const int lB = (rowBase & (NL - 1));
#pragma unroll
        for (int mt = 0; mt < 4; mt++) {
            const int l0 = lB + wm + mt * 16 + g;
#pragma unroll
            for (int nt = 0; nt < 4; nt++) {
                const int a = colBase + wn + nt * 8 + tig * 2;
                float* cp0 = C + (size_t)(bb * NA + a) * NL;
                float* cp1 = C + (size_t)(bb * NA + a + 1) * NL;
                cp0[l0]     = __uint_as_float(f2tf32(acc[mt][nt][0]));
                cp1[l0]     = __uint_as_float(f2tf32(acc[mt][nt][1]));
                cp0[l0 + 8] = __uint_as_float(f2tf32(acc[mt][nt][2]));
                cp1[l0 + 8] = __uint_as_float(f2tf32(acc[mt][nt][3]));
            }
        }
    } else {  // mode 5
        const int bb = rowBase >> 10;
        const int lB = (rowBase & (NL - 1));
#pragma unroll
        for (int mt = 0; mt < 4; mt++) {
            const int l0 = lB + wm + mt * 16 + g;
#pragma unroll
            for (int nt = 0; nt < 4; nt++) {
                const int a = colBase + wn + nt * 8 + tig * 2;
                const int hh = a >> 6, d = a & 63;
                float* cp = C + ((size_t)(bb * NH + hh) * NL + l0) * NDH + d;
                *(float2*)cp = make_float2(__uint_as_float(f2tf32(acc[mt][nt][0])),
                                           __uint_as_float(f2tf32(acc[mt][nt][1])));
                *(float2*)(cp + 8 * NDH) = make_float2(__uint_as_float(f2tf32(acc[mt][nt][2])),
                                                       __uint_as_float(f2tf32(acc[mt][nt][3])));
            }
        }
    }
}

// ------ flash attention: no-max softmax, cp.async K/V, raw-f32 P store -----
#define ATT_LD 68
#define ATT_TILE (64 * ATT_LD)
#define ATT_SMEM ((4 * ATT_TILE + 8 * 16 * ATT_LD) * 4 + NL * 4)  // 108544 B

__global__ __launch_bounds__(256, 2)
void attn_tc(const float* __restrict__ pool_c, float* __restrict__ pool,
             const int* __restrict__ mask)
{
    extern __shared__ uint32_t sm[];
    uint32_t* Ks = sm;
    uint32_t* Vs = Ks + 2 * ATT_TILE;
    uint32_t* Ps = Vs + 2 * ATT_TILE;
    float* msks = (float*)(Ps + 8 * 16 * ATT_LD);

    const int tid = threadIdx.x, lane = tid & 31, wid = tid >> 5;
    const int g = lane >> 2, tig = lane & 3;
    const int qb = blockIdx.x, bh = blockIdx.y;
    const int b = bh >> 4, hoff = (bh & 15) * NDH;

    const float* Qbase = pool_c + F_QH + ((size_t)bh * NL + qb * 128) * NDH;
    const float* Kbase = pool_c + F_KH + (size_t)bh * NL * NDH;
    const float* Vbase = pool_c + F_VT + (size_t)(b * NA + hoff) * NL;
    float* Ctx = pool + F_CTX;
    uint32_t* Pw = Ps + wid * 16 * ATT_LD;

    const int rr = lane & 7, qq = lane >> 3;
    const uint32_t ksb = __cvta_generic_to_shared(Ks);
    const uint32_t vsb = __cvta_generic_to_shared(Vs);
    const uint32_t pwb = __cvta_generic_to_shared(Pw);
    const uint32_t tileB = ATT_TILE * 4;
    uint32_t kvoff[4];
#pragma unroll
    for (int p = 0; p < 4; p++)
        kvoff[p] = ((p * 16 + (qq >> 1) * 8 + rr) * ATT_LD + (qq & 1) * 4) * 4;
    const uint32_t apoff = (((qq & 1) * 8 + rr) * ATT_LD + (qq >> 1) * 4) * 4;

    const int lr = tid >> 2, lc = (tid & 3) << 2;
    auto load_tile = [&](int jb, int buf) {
        const uint32_t off = buf * tileB;
#pragma unroll
        for (int i = 0; i < 4; i++) {
            const int c4 = lc + (i << 4);
            const uint32_t d = off + (lr * ATT_LD + c4) * 4;
            cp_async16(ksb + d, &Kbase[(size_t)(jb * 64 + lr) * 64 + c4]);
            cp_async16(vsb + d, &Vbase[(size_t)lr * NL + jb * 64 + c4]);
        }
        cp_commit();
    };

    for (int i = tid; i < NL; i += 256)
        msks[i] = (1.0f - (float)mask[b * NL + i]) * -100000.0f;

    uint32_t aq[8][4];
    {
        const int r0 = wid * 16 + g;
#pragma unroll
        for (int ks = 0; ks < 8; ks++) {
            aq[ks][0] = __float_as_uint(Qbase[(size_t)r0     * 64 + ks*8 + tig    ] * FSCALE);
            aq[ks][1] = __float_as_uint(Qbase[(size_t)(r0+8) * 64 + ks*8 + tig    ] * FSCALE);
            aq[ks][2] = __float_as_uint(Qbase[(size_t)r0     * 64 + ks*8 + tig + 4] * FSCALE);
            aq[ks][3] = __float_as_uint(Qbase[(size_t)(r0+8) * 64 + ks*8 + tig + 4] * FSCALE);
        }
    }

    float oacc[8][4];
#pragma unroll
    for (int nt = 0; nt < 8; nt++)
#pragma unroll
        for (int e = 0; e < 4; e++) oacc[nt][e] = 0.f;
    float lr0 = 0.f, lr1 = 0.f;

    load_tile(0, 0);

    for (int jb = 0; jb < 16; jb++) {
        cp_wait<0>();
        __syncthreads();
        if (jb + 1 < 16) load_tile(jb + 1, (jb + 1) & 1);

        const uint32_t bo32 = (jb & 1) * tileB;

        float s[8][4];
#pragma unroll
        for (int nt = 0; nt < 8; nt++)
            s[nt][0] = s[nt][1] = s[nt][2] = s[nt][3] = 0.f;
#pragma unroll
        for (int ks = 0; ks < 8; ks++) {
#pragma unroll
            for (int p = 0; p < 4; p++) {
                uint32_t t[4];
                ldsm_x4(t, ksb + bo32 + kvoff[p] + ks * 32);
                mma_tf32(s[2*p],   aq[ks], &t[0]);
                mma_tf32(s[2*p+1], aq[ks], &t[2]);
            }
        }

        float rs0 = 0.f, rs1 = 0.f;
#pragma unroll
        for (int nt = 0; nt < 8; nt++) {
            float2 mv = *(const float2*)&msks[jb*64 + nt*8 + tig*2];
            s[nt][0] = __expf(s[nt][0] + mv.x); rs0 += s[nt][0];
            s[nt][1] = __expf(s[nt][1] + mv.y); rs0 += s[nt][1];
            s[nt][2] = __expf(s[nt][2] + mv.x); rs1 += s[nt][2];
            s[nt][3] = __expf(s[nt][3] + mv.y); rs1 += s[nt][3];
        }
        rs0 += __shfl_xor_sync(0xffffffffu, rs0, 1);
        rs0 += __shfl_xor_sync(0xffffffffu, rs0, 2);
        rs1 += __shfl_xor_sync(0xffffffffu, rs1, 1);
        rs1 += __shfl_xor_sync(0xffffffffu, rs1, 2);
        lr0 += rs0;
        lr1 += rs1;

        __syncwarp();
#pragma unroll
        for (int nt = 0; nt < 8; nt++) {
            *(uint2*)&Pw[g       * ATT_LD + nt*8 + tig*2] =
                make_uint2(__float_as_uint(s[nt][0]), __float_as_uint(s[nt][1]));
            *(uint2*)&Pw[(g + 8) * ATT_LD + nt*8 + tig*2] =
                make_uint2(__float_as_uint(s[nt][2]), __float_as_uint(s[nt][3]));
        }
        __syncwarp();

#pragma unroll
        for (int ks = 0; ks < 8; ks++) {
            uint32_t ap[4];
            ldsm_x4(ap, pwb + apoff + ks * 32);
#pragma unroll
            for (int p = 0; p < 4; p++) {
                uint32_t t[4];
                ldsm_x4(t, vsb + bo32 + kvoff[p] + ks * 32);
                mma_tf32(oacc[2*p],   ap, &t[0]);
                mma_tf32(oacc[2*p+1], ap, &t[2]);
            }
        }
    }

    const float inv0 = 1.0f / lr0, inv1 = 1.0f / lr1;
    const int q0 = qb * 128 + wid * 16 + g;
    float* Ob = Ctx + ((size_t)(b * NL + q0)) * NA + hoff;
#pragma unroll
    for (int nt = 0; nt < 8; nt++) {
        const int co = nt * 8 + tig * 2;
        *(float2*)&Ob[co] = make_float2(
            __uint_as_float(f2tf32(oacc[nt][0] * inv0)),
            __uint_as_float(f2tf32(oacc[nt][1] * inv0)));
        *(float2*)&Ob[(size_t)8 * NA + co] = make_float2(
            __uint_as_float(f2tf32(oacc[nt][2] * inv1)),
            __uint_as_float(f2tf32(oacc[nt][3] * inv1)));
    }
}

// ---------------- LayerNorm ----------------
__global__ __launch_bounds__(256)
void ln_kernel(const float* __restrict__ X, const float* __restrict__ gamma,
               const float* __restrict__ beta, float* __restrict__ out)
{
    __shared__ float ssum[8], ssq[8];
    const int row = blockIdx.x, tid = threadIdx.x;
    const float* xr = X + (size_t)row * NA;
    float4 v = *(const float4*)&xr[tid*4];
    float s = v.x + v.y + v.z + v.w;
    float s2 = v.x*v.x + v.y*v.y + v.z*v.z + v.w*v.w;
#pragma unroll
    for (int o = 16; o > 0; o >>= 1) {
        s  += __shfl_xor_sync(0xffffffffu, s,  o);
        s2 += __shfl_xor_sync(0xffffffffu, s2, o);
    }
    if ((tid & 31) == 0) { ssum[tid>>5] = s; ssq[tid>>5] = s2; }
    __syncthreads();
    float ts = 0.f, ts2 = 0.f;
#pragma unroll
    for (int i = 0; i < 8; i++) { ts += ssum[i]; ts2 += ssq[i]; }
    const float mu = ts * (1.f/1024.f);
    const float var = ts2 * (1.f/1024.f) - mu*mu;
    const float rstd = rsqrtf(var + LN_EPS);
    float4 gm = *(const float4*)&gamma[tid*4];
    float4 be = *(const float4*)&beta[tid*4];
    float4 o;
    o.x = (v.x - mu)*rstd*gm.x + be.x;
    o.y = (v.y - mu)*rstd*gm.y + be.y;
    o.z = (v.z - mu)*rstd*gm.z + be.z;
    o.w = (v.w - mu)*rstd*gm.w + be.w;
    *(float4*)&out[(size_t)row*NA + tid*4] = o;
}

// ---------------------------------------------------------------------------
extern "C" void kernel_launch(void* const* d_in, const int* in_sizes, int n_in,
                              void* d_out, int out_size)
{
    const float* x   = (const float*)d_in[0];
    const float* qu  = (const float*)d_in[1];
    const float* Wk  = (const float*)d_in[2];
    const float* Wqs = (const float*)d_in[3];
    const float* Wqo = (const float*)d_in[4];
    const float* Wv  = (const float*)d_in[5];
    const float* Wo  = (const float*)d_in[6];
    const float* bo  = (const float*)d_in[7];
    const float* gam = (const float*)d_in[8];
    const float* bet = (const float*)d_in[9];
    const int*   msk = (const int*)d_in[10];
    float* out = (float*)d_out;

    float* pool = nullptr;
    cudaGetSymbolAddress((void**)&pool, g_scratch);

    static bool attrSet = false;
    if (!attrSet) {
        cudaFuncSetAttribute(gemm_all, cudaFuncAttributeMaxDynamicSharedMemorySize, GEMM_SMEM);
        cudaFuncSetAttribute(attn_tc, cudaFuncAttributeMaxDynamicSharedMemorySize, ATT_SMEM);
        attrSet = true;
    }

    round_kernel<<<dim3(NM*ND/1024, 1, 7), 256>>>(x, qu, Wqs, Wqo, Wk, Wv, Wo, pool);

    gemm_all<<<dim3(NA/128, NM/128, 3), 256, GEMM_SMEM>>>(0, pool, bo, pool);

    attn_tc<<<dim3(NL/128, NB*NH), 256, ATT_SMEM>>>(pool, pool, msk);

    gemm_all<<<dim3(NA/128, NM/128, 1), 256, GEMM_SMEM>>>(3, pool, bo, pool);

    ln_kernel<<<NM, 256>>>(pool + F_O1, gam, bet, out);
}